// round 5
// baseline (speedup 1.0000x reference)
#include <cuda_runtime.h>
#include <cstdint>

// PointSample: bilinear grid_sample, align_corners=False, border clamp.
// features: [B=8, H=256, W=256, C=128] fp32 (channels-last)
// grid:     [B=8, P=8192, 2] fp32, coords in [0,1]
// out:      [B=8, P=8192, C=128] fp32
//
// One warp per point. Lane l handles channels [4l, 4l+4) via float4.
// Per corner: one coalesced 512B warp load. 4 independent loads/lane (MLP=4).

namespace {
constexpr int B = 8;
constexpr int H = 256;
constexpr int W = 256;
constexpr int C = 128;
constexpr int P = 8192;
constexpr int CVEC = C / 4;          // 32 float4 per row == one per lane
constexpr int NPOINTS = B * P;       // 65536 warps total
constexpr int THREADS = 256;         // 8 warps / block
constexpr int BLOCKS = (NPOINTS * 32) / THREADS;  // 8192
}

__global__ __launch_bounds__(THREADS)
void pointsample_kernel(const float* __restrict__ feat,
                        const float* __restrict__ grid,
                        float* __restrict__ out) {
    const int gwarp = (blockIdx.x * THREADS + threadIdx.x) >> 5;   // point index in [0, B*P)
    const int lane  = threadIdx.x & 31;

    // grid stored as [B, P, 2] -> flat float2 per point (uniform broadcast load)
    const float2 g = reinterpret_cast<const float2*>(grid)[gwarp];

    // normalize to [-1,1], then unnormalize (align_corners=False)
    const float gx = g.x * 2.0f - 1.0f;
    const float gy = g.y * 2.0f - 1.0f;
    const float ix = ((gx + 1.0f) * (float)W - 1.0f) * 0.5f;
    const float iy = ((gy + 1.0f) * (float)H - 1.0f) * 0.5f;

    const float x0f = floorf(ix);
    const float y0f = floorf(iy);
    const float wx = ix - x0f;
    const float wy = iy - y0f;

    const int x0i = (int)x0f;
    const int y0i = (int)y0f;
    const int x0 = min(max(x0i,     0), W - 1);
    const int x1 = min(max(x0i + 1, 0), W - 1);
    const int y0 = min(max(y0i,     0), H - 1);
    const int y1 = min(max(y0i + 1, 0), H - 1);

    const int b = gwarp >> 13;  // gwarp / P  (P = 8192)
    const float4* __restrict__ fb =
        reinterpret_cast<const float4*>(feat) + (size_t)b * H * W * CVEC;

    // 4 independent coalesced loads (512B per corner per warp)
    const float4 c00 = fb[(y0 * W + x0) * CVEC + lane];
    const float4 c01 = fb[(y0 * W + x1) * CVEC + lane];
    const float4 c10 = fb[(y1 * W + x0) * CVEC + lane];
    const float4 c11 = fb[(y1 * W + x1) * CVEC + lane];

    const float w00 = (1.0f - wy) * (1.0f - wx);
    const float w01 = (1.0f - wy) * wx;
    const float w10 = wy * (1.0f - wx);
    const float w11 = wy * wx;

    float4 r;
    r.x = c00.x * w00 + c01.x * w01 + c10.x * w10 + c11.x * w11;
    r.y = c00.y * w00 + c01.y * w01 + c10.y * w10 + c11.y * w11;
    r.z = c00.z * w00 + c01.z * w01 + c10.z * w10 + c11.z * w11;
    r.w = c00.w * w00 + c01.w * w01 + c10.w * w10 + c11.w * w11;

    reinterpret_cast<float4*>(out)[(size_t)gwarp * CVEC + lane] = r;
}

extern "C" void kernel_launch(void* const* d_in, const int* in_sizes, int n_in,
                              void* d_out, int out_size) {
    const float* feat = (const float*)d_in[0];   // [8,256,256,128]
    const float* grid = (const float*)d_in[1];   // [8,8192,2]
    float* out = (float*)d_out;                  // [8,8192,128]
    (void)in_sizes; (void)n_in; (void)out_size;
    pointsample_kernel<<<BLOCKS, THREADS>>>(feat, grid, out);
}

// round 6
// speedup vs baseline: 1.0708x; 1.0708x over previous
#include <cuda_runtime.h>
#include <cstdint>

// PointSample: bilinear grid_sample, align_corners=False, border clamp.
// features: [B=8, H=256, W=256, C=128] fp32 (channels-last)
// grid:     [B=8, P=8192, 2] fp32, coords in [0,1]
// out:      [B=8, P=8192, C=128] fp32
//
// One point per HALF-warp. Each lane owns 2 float4 chunks per corner:
// 8 independent LDG.128 in flight per lane (MLP=8, 2x previous kernel).
// Streaming stores (__stcs) keep output writes from polluting L2.

namespace {
constexpr int B = 8;
constexpr int H = 256;
constexpr int W = 256;
constexpr int C = 128;
constexpr int P = 8192;
constexpr int CVEC = C / 4;            // 32 float4 per feature row
constexpr int NPOINTS = B * P;         // 65536
constexpr int THREADS = 256;           // 8 warps -> 16 points per block
constexpr int PTS_PER_BLOCK = (THREADS / 32) * 2;
constexpr int BLOCKS = NPOINTS / PTS_PER_BLOCK;  // 4096
}

__global__ __launch_bounds__(THREADS, 5)
void pointsample_kernel(const float* __restrict__ feat,
                        const float* __restrict__ grid,
                        float* __restrict__ out) {
    const int tid   = blockIdx.x * THREADS + threadIdx.x;
    const int lane  = threadIdx.x & 31;
    const int half  = lane >> 4;                 // 0 or 1
    const int hl    = lane & 15;                 // lane within half-warp
    const int p     = (tid >> 5) * 2 + half;     // point index in [0, B*P)

    // grid: [B, P, 2] -> flat float2 per point (broadcast within half-warp)
    const float2 g = __ldg(&reinterpret_cast<const float2*>(grid)[p]);

    // normalize to [-1,1], then unnormalize (align_corners=False)
    const float gx = g.x * 2.0f - 1.0f;
    const float gy = g.y * 2.0f - 1.0f;
    const float ix = ((gx + 1.0f) * (float)W - 1.0f) * 0.5f;
    const float iy = ((gy + 1.0f) * (float)H - 1.0f) * 0.5f;

    const float x0f = floorf(ix);
    const float y0f = floorf(iy);
    const float wx = ix - x0f;
    const float wy = iy - y0f;

    const int x0i = (int)x0f;
    const int y0i = (int)y0f;
    const int x0 = min(max(x0i,     0), W - 1);
    const int x1 = min(max(x0i + 1, 0), W - 1);
    const int y0 = min(max(y0i,     0), H - 1);
    const int y1 = min(max(y0i + 1, 0), H - 1);

    const int b = p >> 13;  // p / P
    const float4* __restrict__ fb =
        reinterpret_cast<const float4*>(feat) + (size_t)b * H * W * CVEC;

    const int r00 = (y0 * W + x0) * CVEC;
    const int r01 = (y0 * W + x1) * CVEC;
    const int r10 = (y1 * W + x0) * CVEC;
    const int r11 = (y1 * W + x1) * CVEC;

    const int c0 = hl;        // chunk 0: bytes [0,256) of the row
    const int c1 = hl + 16;   // chunk 1: bytes [256,512)

    // 8 independent coalesced loads per lane (MLP = 8)
    const float4 a00 = fb[r00 + c0];
    const float4 a01 = fb[r01 + c0];
    const float4 a10 = fb[r10 + c0];
    const float4 a11 = fb[r11 + c0];
    const float4 b00 = fb[r00 + c1];
    const float4 b01 = fb[r01 + c1];
    const float4 b10 = fb[r10 + c1];
    const float4 b11 = fb[r11 + c1];

    const float w00 = (1.0f - wy) * (1.0f - wx);
    const float w01 = (1.0f - wy) * wx;
    const float w10 = wy * (1.0f - wx);
    const float w11 = wy * wx;

    float4 r0, r1;
    r0.x = a00.x * w00 + a01.x * w01 + a10.x * w10 + a11.x * w11;
    r0.y = a00.y * w00 + a01.y * w01 + a10.y * w10 + a11.y * w11;
    r0.z = a00.z * w00 + a01.z * w01 + a10.z * w10 + a11.z * w11;
    r0.w = a00.w * w00 + a01.w * w01 + a10.w * w10 + a11.w * w11;
    r1.x = b00.x * w00 + b01.x * w01 + b10.x * w10 + b11.x * w11;
    r1.y = b00.y * w00 + b01.y * w01 + b10.y * w10 + b11.y * w11;
    r1.z = b00.z * w00 + b01.z * w01 + b10.z * w10 + b11.z * w11;
    r1.w = b00.w * w00 + b01.w * w01 + b10.w * w10 + b11.w * w11;

    // Streaming stores: output is write-once, keep it out of L2's way.
    float4* __restrict__ op = reinterpret_cast<float4*>(out) + (size_t)p * CVEC;
    __stcs(op + c0, r0);
    __stcs(op + c1, r1);
}

extern "C" void kernel_launch(void* const* d_in, const int* in_sizes, int n_in,
                              void* d_out, int out_size) {
    const float* feat = (const float*)d_in[0];   // [8,256,256,128]
    const float* grid = (const float*)d_in[1];   // [8,8192,2]
    float* out = (float*)d_out;                  // [8,8192,128]
    (void)in_sizes; (void)n_in; (void)out_size;
    pointsample_kernel<<<BLOCKS, THREADS>>>(feat, grid, out);
}

// round 7
// speedup vs baseline: 1.1846x; 1.1063x over previous
#include <cuda_runtime.h>
#include <cstdint>

// PointSample: bilinear grid_sample, align_corners=False, border clamp.
// features: [B=8, H=256, W=256, C=128] fp32 (channels-last)
// grid:     [B=8, P=8192, 2] fp32, coords in [0,1]
// out:      [B=8, P=8192, C=128] fp32
//
// One point per QUARTER-warp (8 lanes). Each lane owns 4 float4 chunks per
// corner row: 16 independent LDG.128 in flight per lane (MLP=16).
// __ldcs on features (streaming reads), __stcs on output (streaming writes).

namespace {
constexpr int B = 8;
constexpr int H = 256;
constexpr int W = 256;
constexpr int C = 128;
constexpr int P = 8192;
constexpr int CVEC = C / 4;            // 32 float4 per feature row
constexpr int NPOINTS = B * P;         // 65536
constexpr int THREADS = 256;           // 8 warps -> 32 points per block
constexpr int PTS_PER_BLOCK = (THREADS / 32) * 4;         // 32
constexpr int BLOCKS = NPOINTS / PTS_PER_BLOCK;           // 2048
}

__global__ __launch_bounds__(THREADS, 3)
void pointsample_kernel(const float* __restrict__ feat,
                        const float* __restrict__ grid,
                        float* __restrict__ out) {
    const int tid  = blockIdx.x * THREADS + threadIdx.x;
    const int lane = threadIdx.x & 31;
    const int q    = lane >> 3;                  // quarter id 0..3
    const int ql   = lane & 7;                   // lane within quarter
    const int p    = (tid >> 5) * 4 + q;         // point index in [0, B*P)

    // grid: [B, P, 2] -> flat float2 per point (broadcast within quarter-warp)
    const float2 g = __ldg(&reinterpret_cast<const float2*>(grid)[p]);

    // normalize to [-1,1], then unnormalize (align_corners=False)
    const float gx = g.x * 2.0f - 1.0f;
    const float gy = g.y * 2.0f - 1.0f;
    const float ix = ((gx + 1.0f) * (float)W - 1.0f) * 0.5f;
    const float iy = ((gy + 1.0f) * (float)H - 1.0f) * 0.5f;

    const float x0f = floorf(ix);
    const float y0f = floorf(iy);
    const float wx = ix - x0f;
    const float wy = iy - y0f;

    const int x0i = (int)x0f;
    const int y0i = (int)y0f;
    const int x0 = min(max(x0i,     0), W - 1);
    const int x1 = min(max(x0i + 1, 0), W - 1);
    const int y0 = min(max(y0i,     0), H - 1);
    const int y1 = min(max(y0i + 1, 0), H - 1);

    const int b = p >> 13;  // p / P
    const float4* __restrict__ fb =
        reinterpret_cast<const float4*>(feat) + (size_t)b * H * W * CVEC;

    const float4* r00 = fb + (y0 * W + x0) * CVEC + ql;
    const float4* r01 = fb + (y0 * W + x1) * CVEC + ql;
    const float4* r10 = fb + (y1 * W + x0) * CVEC + ql;
    const float4* r11 = fb + (y1 * W + x1) * CVEC + ql;

    // 16 independent streaming loads per lane (MLP = 16).
    // Chunk k covers bytes [128k + 16*ql, ...) of each 512B row.
    float4 a00 = __ldcs(r00 +  0), a01 = __ldcs(r01 +  0), a10 = __ldcs(r10 +  0), a11 = __ldcs(r11 +  0);
    float4 b00 = __ldcs(r00 +  8), b01 = __ldcs(r01 +  8), b10 = __ldcs(r10 +  8), b11 = __ldcs(r11 +  8);
    float4 c00 = __ldcs(r00 + 16), c01 = __ldcs(r01 + 16), c10 = __ldcs(r10 + 16), c11 = __ldcs(r11 + 16);
    float4 d00 = __ldcs(r00 + 24), d01 = __ldcs(r01 + 24), d10 = __ldcs(r10 + 24), d11 = __ldcs(r11 + 24);

    const float w00 = (1.0f - wy) * (1.0f - wx);
    const float w01 = (1.0f - wy) * wx;
    const float w10 = wy * (1.0f - wx);
    const float w11 = wy * wx;

    float4* __restrict__ op = reinterpret_cast<float4*>(out) + (size_t)p * CVEC + ql;

    float4 r;
    r.x = a00.x * w00 + a01.x * w01 + a10.x * w10 + a11.x * w11;
    r.y = a00.y * w00 + a01.y * w01 + a10.y * w10 + a11.y * w11;
    r.z = a00.z * w00 + a01.z * w01 + a10.z * w10 + a11.z * w11;
    r.w = a00.w * w00 + a01.w * w01 + a10.w * w10 + a11.w * w11;
    __stcs(op + 0, r);

    r.x = b00.x * w00 + b01.x * w01 + b10.x * w10 + b11.x * w11;
    r.y = b00.y * w00 + b01.y * w01 + b10.y * w10 + b11.y * w11;
    r.z = b00.z * w00 + b01.z * w01 + b10.z * w10 + b11.z * w11;
    r.w = b00.w * w00 + b01.w * w01 + b10.w * w10 + b11.w * w11;
    __stcs(op + 8, r);

    r.x = c00.x * w00 + c01.x * w01 + c10.x * w10 + c11.x * w11;
    r.y = c00.y * w00 + c01.y * w01 + c10.y * w10 + c11.y * w11;
    r.z = c00.z * w00 + c01.z * w01 + c10.z * w10 + c11.z * w11;
    r.w = c00.w * w00 + c01.w * w01 + c10.w * w10 + c11.w * w11;
    __stcs(op + 16, r);

    r.x = d00.x * w00 + d01.x * w01 + d10.x * w10 + d11.x * w11;
    r.y = d00.y * w00 + d01.y * w01 + d10.y * w10 + d11.y * w11;
    r.z = d00.z * w00 + d01.z * w01 + d10.z * w10 + d11.z * w11;
    r.w = d00.w * w00 + d01.w * w01 + d10.w * w10 + d11.w * w11;
    __stcs(op + 24, r);
}

extern "C" void kernel_launch(void* const* d_in, const int* in_sizes, int n_in,
                              void* d_out, int out_size) {
    const float* feat = (const float*)d_in[0];   // [8,256,256,128]
    const float* grid = (const float*)d_in[1];   // [8,8192,2]
    float* out = (float*)d_out;                  // [8,8192,128]
    (void)in_sizes; (void)n_in; (void)out_size;
    pointsample_kernel<<<BLOCKS, THREADS>>>(feat, grid, out);
}